// round 5
// baseline (speedup 1.0000x reference)
#include <cuda_runtime.h>
#include <cuda_bf16.h>

#define NBX 2048
#define NBY 2048
#define HEIGHT 4096
#define BIN_AREA 4.0f

// 256-bit load with L2 evict_first (sm_103a requires .v8.b32 for evict hints).
// Input map is dead after one read per replay; don't displace output in L2.
__device__ __forceinline__ void ld_ef8(const int* p, int* v) {
    asm volatile("ld.global.nc.L2::evict_first.v8.b32 {%0,%1,%2,%3,%4,%5,%6,%7}, [%8];"
                 : "=r"(v[0]), "=r"(v[1]), "=r"(v[2]), "=r"(v[3]),
                   "=r"(v[4]), "=r"(v[5]), "=r"(v[6]), "=r"(v[7])
                 : "l"(p));
}

// 256-bit store with L2 evict_last: output (112MB) is rewritten every graph
// replay; keeping it dirty-resident in the 126MB L2 kills DRAM writeback.
__device__ __forceinline__ void st_el8(float* p, const float* v) {
    asm volatile("st.global.L2::evict_last.v8.b32 [%0], {%1,%2,%3,%4,%5,%6,%7,%8};"
                 :: "l"(p), "f"(v[0]), "f"(v[1]), "f"(v[2]), "f"(v[3]),
                    "f"(v[4]), "f"(v[5]), "f"(v[6]), "f"(v[7])
                 : "memory");
}

// Each thread computes 8 bins along j (y-bin axis).
// Bin (i,j) aggregates site types at (2i,2j),(2i,2j+1),(2i+1,2j),(2i+1,2j+1).
// Per-site area replicates reference fp32 rounding: wx = rn(xf+nw)-xf, wy = rn(yf+nh)-yf.
__global__ __launch_bounds__(256) void demand_map_kernel(
    const int* __restrict__ st,
    const float* __restrict__ nsx,
    const float* __restrict__ nsy,
    float* __restrict__ out)
{
    int tid = blockIdx.x * blockDim.x + threadIdx.x;   // 2048 * 256 threads
    int i  = tid >> 8;          // x-bin row (0..2047)
    int jq = tid & 255;         // group of 8 y-bins
    int ybase = jq << 4;        // 16 site columns per thread
    int x0 = i << 1;
    int x1 = x0 + 1;

    // per-type node sizes (types 1..3 -> slots 0..2)
    float nwx0 = __ldg(&nsx[1]), nwx1 = __ldg(&nsx[2]), nwx2 = __ldg(&nsx[3]);
    float nwy0 = __ldg(&nsy[1]), nwy1 = __ldg(&nsy[2]), nwy2 = __ldg(&nsy[3]);

    float xf0 = (float)x0, xf1 = (float)x1;
    // wx per (row, slot) — exact fp32 replication of reference
    float wxA[3], wxB[3];
    wxA[0] = __fsub_rn(__fadd_rn(xf0, nwx0), xf0);
    wxA[1] = __fsub_rn(__fadd_rn(xf0, nwx1), xf0);
    wxA[2] = __fsub_rn(__fadd_rn(xf0, nwx2), xf0);
    wxB[0] = __fsub_rn(__fadd_rn(xf1, nwx0), xf1);
    wxB[1] = __fsub_rn(__fadd_rn(xf1, nwx1), xf1);
    wxB[2] = __fsub_rn(__fadd_rn(xf1, nwx2), xf1);

    const int* r0 = st + (size_t)x0 * HEIGHT + ybase;
    const int* r1 = st + (size_t)x1 * HEIGHT + ybase;
    int ta[16], tb[16];
    ld_ef8(r0,     ta);
    ld_ef8(r0 + 8, ta + 8);
    ld_ef8(r1,     tb);
    ld_ef8(r1 + 8, tb + 8);

    float o0[8], o5[8], o6[8];

    #pragma unroll
    for (int b = 0; b < 8; b++) {
        float c0 = 0.0f, c1 = 0.0f, c2 = 0.0f;
        #pragma unroll
        for (int s = 0; s < 2; s++) {
            int ys = ybase + (b << 1) + s;
            float yf = (float)ys;
            // wy per slot for this site column
            float wy0 = __fsub_rn(__fadd_rn(yf, nwy0), yf);
            float wy1 = __fsub_rn(__fadd_rn(yf, nwy1), yf);
            float wy2 = __fsub_rn(__fadd_rn(yf, nwy2), yf);
            int t0 = ta[(b << 1) + s];
            int t1 = tb[(b << 1) + s];
            // branchless predicated accumulation (types are random -> avoid divergence)
            c0 += (t0 == 1) ? __fmul_rn(wxA[0], wy0) : 0.0f;
            c1 += (t0 == 2) ? __fmul_rn(wxA[1], wy1) : 0.0f;
            c2 += (t0 == 3) ? __fmul_rn(wxA[2], wy2) : 0.0f;
            c0 += (t1 == 1) ? __fmul_rn(wxB[0], wy0) : 0.0f;
            c1 += (t1 == 2) ? __fmul_rn(wxB[1], wy1) : 0.0f;
            c2 += (t1 == 3) ? __fmul_rn(wxB[2], wy2) : 0.0f;
        }
        o0[b] = BIN_AREA - c0;
        o5[b] = BIN_AREA - c1;
        o6[b] = BIN_AREA - c2;
    }

    size_t plane = (size_t)NBX * NBY;           // floats per plane
    float* p = out + (size_t)i * NBY + (ybase >> 1);  // 8 floats per thread, 32B aligned

    st_el8(p + 0 * plane, o0);
    st_el8(p + 1 * plane, o0);
    st_el8(p + 2 * plane, o0);
    st_el8(p + 3 * plane, o0);
    st_el8(p + 4 * plane, o0);
    st_el8(p + 5 * plane, o5);
    st_el8(p + 6 * plane, o6);
}

extern "C" void kernel_launch(void* const* d_in, const int* in_sizes, int n_in,
                              void* d_out, int out_size) {
    const int*   st  = (const int*)d_in[0];     // site_type_map [4096*4096] int32
    const float* nsx = (const float*)d_in[1];   // node_size_x [4]
    const float* nsy = (const float*)d_in[2];   // node_size_y [4]
    float* out = (float*)d_out;                 // [7, 2048, 2048] float32

    // 2048 bin-rows * 256 threads/row (8 bins each) = 524,288 threads
    dim3 block(256);
    dim3 grid((2048u * 256u) / 256u);
    demand_map_kernel<<<grid, block>>>(st, nsx, nsy, out);
}

// round 6
// speedup vs baseline: 1.1363x; 1.1363x over previous
#include <cuda_runtime.h>
#include <cuda_bf16.h>

#define NBX 2048
#define NBY 2048
#define HEIGHT 4096
#define BIN_AREA 4.0f

// Each thread computes 4 bins along j (y-bin axis).
// Bin (i,j) aggregates site types at (2i,2j),(2i,2j+1),(2i+1,2j),(2i+1,2j+1).
// Per-site area replicates reference fp32 rounding: wx = rn(xf+nw)-xf, wy = rn(yf+nh)-yf.
//
// Stores use __stcs (streaming / evict-first): the 112MB output stream must not
// evict the 64MB input map from L2, so the input read is an L2 hit on every
// graph replay.
__global__ __launch_bounds__(256) void demand_map_kernel(
    const int* __restrict__ st,
    const float* __restrict__ nsx,
    const float* __restrict__ nsy,
    float* __restrict__ out)
{
    int tid = blockIdx.x * blockDim.x + threadIdx.x;   // 2048 * 512 threads
    int i  = tid >> 9;          // x-bin row
    int jq = tid & 511;         // group of 4 y-bins
    int ybase = jq << 3;        // 8 site columns per thread
    int x0 = i << 1;
    int x1 = x0 + 1;

    // per-type node sizes (types 1..3 -> slots 0..2)
    float nwx0 = __ldg(&nsx[1]), nwx1 = __ldg(&nsx[2]), nwx2 = __ldg(&nsx[3]);
    float nwy0 = __ldg(&nsy[1]), nwy1 = __ldg(&nsy[2]), nwy2 = __ldg(&nsy[3]);

    float xf0 = (float)x0, xf1 = (float)x1;
    // wx per (row, slot) — exact fp32 replication of reference
    float wxA[3], wxB[3];
    wxA[0] = __fsub_rn(__fadd_rn(xf0, nwx0), xf0);
    wxA[1] = __fsub_rn(__fadd_rn(xf0, nwx1), xf0);
    wxA[2] = __fsub_rn(__fadd_rn(xf0, nwx2), xf0);
    wxB[0] = __fsub_rn(__fadd_rn(xf1, nwx0), xf1);
    wxB[1] = __fsub_rn(__fadd_rn(xf1, nwx1), xf1);
    wxB[2] = __fsub_rn(__fadd_rn(xf1, nwx2), xf1);

    const int4* r0 = (const int4*)(st + (size_t)x0 * HEIGHT + ybase);
    const int4* r1 = (const int4*)(st + (size_t)x1 * HEIGHT + ybase);
    // default-priority loads: input should allocate and persist in L2
    int4 a0 = __ldg(&r0[0]);
    int4 a1 = __ldg(&r0[1]);
    int4 b0 = __ldg(&r1[0]);
    int4 b1 = __ldg(&r1[1]);

    int ta[8] = {a0.x, a0.y, a0.z, a0.w, a1.x, a1.y, a1.z, a1.w};
    int tb[8] = {b0.x, b0.y, b0.z, b0.w, b1.x, b1.y, b1.z, b1.w};

    float o0[4], o5[4], o6[4];

    #pragma unroll
    for (int b = 0; b < 4; b++) {
        float c0 = 0.0f, c1 = 0.0f, c2 = 0.0f;
        #pragma unroll
        for (int s = 0; s < 2; s++) {
            int ys = ybase + (b << 1) + s;
            float yf = (float)ys;
            // wy per slot for this site column
            float wy0 = __fsub_rn(__fadd_rn(yf, nwy0), yf);
            float wy1 = __fsub_rn(__fadd_rn(yf, nwy1), yf);
            float wy2 = __fsub_rn(__fadd_rn(yf, nwy2), yf);
            int t0 = ta[(b << 1) + s];
            int t1 = tb[(b << 1) + s];
            // branchless predicated accumulation (types are random -> avoid divergence)
            c0 += (t0 == 1) ? __fmul_rn(wxA[0], wy0) : 0.0f;
            c1 += (t0 == 2) ? __fmul_rn(wxA[1], wy1) : 0.0f;
            c2 += (t0 == 3) ? __fmul_rn(wxA[2], wy2) : 0.0f;
            c0 += (t1 == 1) ? __fmul_rn(wxB[0], wy0) : 0.0f;
            c1 += (t1 == 2) ? __fmul_rn(wxB[1], wy1) : 0.0f;
            c2 += (t1 == 3) ? __fmul_rn(wxB[2], wy2) : 0.0f;
        }
        o0[b] = BIN_AREA - c0;
        o5[b] = BIN_AREA - c1;
        o6[b] = BIN_AREA - c2;
    }

    float4 v0 = make_float4(o0[0], o0[1], o0[2], o0[3]);
    float4 v5 = make_float4(o5[0], o5[1], o5[2], o5[3]);
    float4 v6 = make_float4(o6[0], o6[1], o6[2], o6[3]);

    float4* o = (float4*)out;
    size_t plane4 = (size_t)NBX * NBY / 4;      // 1,048,576 float4 per plane
    size_t p = (size_t)i * 512 + jq;            // float4 index within plane

    // streaming stores: evict-first so the output stream doesn't kill
    // the input map's L2 residency across graph replays
    __stcs(&o[0 * plane4 + p], v0);
    __stcs(&o[1 * plane4 + p], v0);
    __stcs(&o[2 * plane4 + p], v0);
    __stcs(&o[3 * plane4 + p], v0);
    __stcs(&o[4 * plane4 + p], v0);
    __stcs(&o[5 * plane4 + p], v5);
    __stcs(&o[6 * plane4 + p], v6);
}

extern "C" void kernel_launch(void* const* d_in, const int* in_sizes, int n_in,
                              void* d_out, int out_size) {
    const int*   st  = (const int*)d_in[0];     // site_type_map [4096*4096] int32
    const float* nsx = (const float*)d_in[1];   // node_size_x [4]
    const float* nsy = (const float*)d_in[2];   // node_size_y [4]
    float* out = (float*)d_out;                 // [7, 2048, 2048] float32

    // 2048 bin-rows * 512 threads/row (4 bins each) = 1,048,576 threads
    dim3 block(256);
    dim3 grid((2048u * 512u) / 256u);
    demand_map_kernel<<<grid, block>>>(st, nsx, nsy, out);
}